// round 1
// baseline (speedup 1.0000x reference)
#include <cuda_runtime.h>

typedef unsigned long long ull;

#define BN 8
#define NPT 256
#define FF 32
#define NRBF_ 50
#define HH 128
#define NM1 255
#define NCOL 512
#define EPSV 1e-6f
#define STRIDE_B (NPT*3 + NPT*FF)   /* 8960 */

__device__ float g_vxf[BN*NPT*3];
__device__ float g_sumv[BN*3];
__device__ float g_trace[BN];

struct SmemLayout {
    float  Wc[NRBF_*NCOL];   // [k][512]: s1W1 | s2W1 | fW1 | mu*s1W1   (102400 B)
    float2 A2[NRBF_*64];     // rbf broadcast-packed [k][pair]           (25600 B)
    float  xs[NPT*3];
    float  ms[NRBF_ + 2];
    float  pd[64];
    float  pr[64*3];
    float  feats_s[FF];
    float  smax[FF];
    float  accst[8][HH];
    float  wpart[8][8];
};

__device__ __forceinline__ float2 unpack2(ull v) {
    float2 r; asm("mov.b64 {%0, %1}, %2;" : "=f"(r.x), "=f"(r.y) : "l"(v)); return r;
}
__device__ __forceinline__ void ffma2(ull &d, ull a, ull b) {
    asm("fma.rn.f32x2 %0, %1, %2, %3;" : "=l"(d) : "l"(a), "l"(b), "l"(d));
}

__global__ void k_init() {
    int t = threadIdx.x;
    if (t < BN*3) g_sumv[t] = 0.f;
    if (t < BN)  g_trace[t] = 0.f;
}

__global__ __launch_bounds__(256, 1) void k_main(
    const float* __restrict__ state,
    const float* __restrict__ mus,
    const float* __restrict__ gammap,
    const float* __restrict__ s1W1, const float* __restrict__ s1b1,
    const float* __restrict__ s1W2, const float* __restrict__ s1b2,
    const float* __restrict__ s2W1, const float* __restrict__ s2b1,
    const float* __restrict__ s2W2, const float* __restrict__ s2b2,
    const float* __restrict__ fW1,  const float* __restrict__ fb1,
    const float* __restrict__ fW2,  const float* __restrict__ fb2,
    float* __restrict__ out)
{
    extern __shared__ char smraw[];
    SmemLayout& S = *reinterpret_cast<SmemLayout*>(smraw);
    const int tid = threadIdx.x;
    const int tx  = tid & 31;
    const int ty  = tid >> 5;
    const float gamma = gammap[0];
    const float n2g   = -2.0f * gamma;
    const float b2s1  = s1b2[0];
    const float b2s2  = s2b2[0];

    // Combined weight matrix into SMEM (once per CTA, reused across all bi)
    for (int e = tid; e < NRBF_*HH; e += 256) {
        int k = e >> 7, h = e & 127;
        float w1 = s1W1[e];
        S.Wc[k*NCOL + h]       = w1;
        S.Wc[k*NCOL + 128 + h] = s2W1[e];
        S.Wc[k*NCOL + 256 + h] = fW1[e];
        S.Wc[k*NCOL + 384 + h] = mus[k] * w1;
    }
    if (tid < NRBF_) S.ms[tid] = mus[tid];

    float w2s1v[4], w2s2v[4];
    #pragma unroll
    for (int q = 0; q < 4; q++) {
        w2s1v[q] = s1W2[tx*4 + q];
        w2s2v[q] = s2W2[tx*4 + q];
    }

    for (int bi = blockIdx.x; bi < BN*NPT; bi += gridDim.x) {
        const int b = bi >> 8;
        const int i = bi & 255;
        const float* st = state + b*STRIDE_B;
        __syncthreads();   // also covers Wc readiness on first iter
        for (int e = tid; e < NPT*3; e += 256) S.xs[e] = st[e];
        if (tid < FF) S.feats_s[tid] = st[NPT*3 + i*FF + tid];
        __syncthreads();

        if (ty == 0) {  // softmax(feats_i) over F=32 by warp 0
            float v = S.feats_s[tx];
            float m = v;
            #pragma unroll
            for (int o = 16; o; o >>= 1) m = fmaxf(m, __shfl_xor_sync(0xffffffffu, m, o));
            float e = __expf(v - m);
            float s = e;
            #pragma unroll
            for (int o = 16; o; o >>= 1) s += __shfl_xor_sync(0xffffffffu, s, o);
            S.smax[tx] = e / s;
        }
        __syncthreads();

        // Per-(b,i) constant part of each hidden pre-activation (feats cols + bias)
        float c1[4], c2[4], cf[4];
        #pragma unroll
        for (int q = 0; q < 4; q++) {
            int h = tx*4 + q;
            float a1 = s1b1[h], a2 = s2b1[h], af = fb1[h];
            for (int f = 0; f < FF; f++) {
                float fe = S.feats_s[f];
                a1 += fe * (s1W1[(NRBF_+f)*HH + h] + s1W1[(NRBF_+FF+f)*HH + h]);
                a2 += fe * (s2W1[(NRBF_+f)*HH + h] + s2W1[(NRBF_+FF+f)*HH + h]);
                af += S.smax[f] * fW1[(NRBF_+f)*HH + h];
            }
            c1[q] = a1; c2[q] = a2; cf[q] = af;
        }
        const float xi0 = S.xs[i*3+0], xi1 = S.xs[i*3+1], xi2 = S.xs[i*3+2];

        float accf0=0.f, accf1=0.f, accf2=0.f, accf3=0.f;
        float vx0=0.f, vy0=0.f, vz0=0.f;
        float wxa=0.f, wya=0.f, wza=0.f;
        float trc=0.f;

        for (int tile = 0; tile < 4; tile++) {
            if (tid < 64) {
                int gp = tile*64 + tid;
                float r0 = 0.f, r1 = 0.f, r2 = 0.f;
                if (gp < NM1) {
                    int j = (gp < i) ? gp : gp + 1;
                    r0 = xi0 - S.xs[j*3+0];
                    r1 = xi1 - S.xs[j*3+1];
                    r2 = xi2 - S.xs[j*3+2];
                }
                S.pd[tid] = sqrtf(r0*r0 + r1*r1 + r2*r2 + EPSV);
                S.pr[tid*3+0] = r0; S.pr[tid*3+1] = r1; S.pr[tid*3+2] = r2;
            }
            __syncthreads();
            for (int e = tid; e < NRBF_*64; e += 256) {
                int k = e >> 6, p = e & 63;
                float t = S.pd[p] - S.ms[k];
                float v = __expf(-gamma * t * t);
                S.A2[e] = make_float2(v, v);
            }
            __syncthreads();

            // GEMM: [64 x 50] @ [50 x 512] with f32x2 packed FMA
            ull acc[4][8][2];
            #pragma unroll
            for (int j = 0; j < 4; j++)
                #pragma unroll
                for (int p = 0; p < 8; p++) { acc[j][p][0] = 0ull; acc[j][p][1] = 0ull; }

            const ull* Arow = reinterpret_cast<const ull*>(S.A2) + ty*8;
            const ull* Wu   = reinterpret_cast<const ull*>(S.Wc) + tx*2;
            #pragma unroll 5
            for (int k = 0; k < NRBF_; k++) {
                ull av[8];
                #pragma unroll
                for (int p = 0; p < 8; p++) av[p] = Arow[k*64 + p];
                #pragma unroll
                for (int j = 0; j < 4; j++) {
                    ulonglong2 bv = *reinterpret_cast<const ulonglong2*>(Wu + k*256 + j*64);
                    #pragma unroll
                    for (int p = 0; p < 8; p++) {
                        ffma2(acc[j][p][0], bv.x, av[p]);
                        ffma2(acc[j][p][1], bv.y, av[p]);
                    }
                }
            }

            // Epilogue: per-pair silu / s1 / s2 / exact d-gradient, warp-level reductions
            #pragma unroll
            for (int p = 0; p < 8; p++) {
                int lp = ty*8 + p;
                int gp = tile*64 + lp;
                float d  = S.pd[lp];
                float r0 = S.pr[lp*3+0], r1 = S.pr[lp*3+1], r2 = S.pr[lp*3+2];
                float s1part = 0.f, s2part = 0.f, gpart = 0.f;
                float afq[4];
                #pragma unroll
                for (int half = 0; half < 2; half++) {
                    float2 v1 = unpack2(acc[0][p][half]);
                    float2 v2 = unpack2(acc[1][p][half]);
                    float2 vf = unpack2(acc[2][p][half]);
                    float2 vp = unpack2(acc[3][p][half]);
                    #pragma unroll
                    for (int sub = 0; sub < 2; sub++) {
                        int q = half*2 + sub;
                        float phi1 = sub ? v1.y : v1.x;
                        float phi2 = sub ? v2.y : v2.x;
                        float phif = sub ? vf.y : vf.x;
                        float psi  = sub ? vp.y : vp.x;
                        float pre1 = phi1 + c1[q];
                        float sig1 = __fdividef(1.f, 1.f + __expf(-pre1));
                        s1part += pre1 * sig1 * w2s1v[q];
                        float dsil = sig1 * (1.f + pre1 * (1.f - sig1));
                        float tq = n2g * (d * phi1 - psi);
                        gpart += w2s1v[q] * dsil * tq;
                        float pre2 = phi2 + c2[q];
                        float sig2 = __fdividef(1.f, 1.f + __expf(-pre2));
                        s2part += pre2 * sig2 * w2s2v[q];
                        float pref = phif + cf[q];
                        float sigf = __fdividef(1.f, 1.f + __expf(-pref));
                        afq[q] = pref * sigf;
                    }
                }
                #pragma unroll
                for (int o = 16; o; o >>= 1) {
                    s1part += __shfl_xor_sync(0xffffffffu, s1part, o);
                    s2part += __shfl_xor_sync(0xffffffffu, s2part, o);
                    gpart  += __shfl_xor_sync(0xffffffffu, gpart,  o);
                }
                if (gp < NM1) {
                    float s1 = s1part + b2s1;
                    float s2 = s2part + b2s2;
                    float r2d = __fdividef(d*d - EPSV, d);   // |r|^2 / d
                    vx0 += r0*s1; vy0 += r1*s1; vz0 += r2*s1;
                    wxa += r0*s2; wya += r1*s2; wza += r2*s2;
                    trc += r2d * gpart + 3.f * s1;
                    accf0 += afq[0]; accf1 += afq[1]; accf2 += afq[2]; accf3 += afq[3];
                }
            }
            __syncthreads();
        } // tiles

        // Combine per-warp partials
        S.accst[ty][tx*4+0] = accf0;
        S.accst[ty][tx*4+1] = accf1;
        S.accst[ty][tx*4+2] = accf2;
        S.accst[ty][tx*4+3] = accf3;
        if (tx == 0) {
            S.wpart[ty][0] = vx0; S.wpart[ty][1] = vy0; S.wpart[ty][2] = vz0;
            S.wpart[ty][3] = wxa; S.wpart[ty][4] = wya; S.wpart[ty][5] = wza;
            S.wpart[ty][6] = trc;
        }
        __syncthreads();
        if (tid < HH) {
            float t = 0.f;
            #pragma unroll
            for (int w = 0; w < 8; w++) t += S.accst[w][tid];
            S.accst[0][tid] = t;
        }
        __syncthreads();
        if (tid < FF) {
            float s = 0.f;
            for (int h = 0; h < HH; h++) s += S.accst[0][h] * fW2[h*FF + tid];
            out[b*STRIDE_B + NPT*3 + i*FF + tid] = fb2[tid] + s * (1.f/255.f);
        }
        if (tid == 0) {
            float v0=0,v1=0,v2=0,w0=0,w1=0,w2=0,tr=0;
            #pragma unroll
            for (int w = 0; w < 8; w++) {
                v0 += S.wpart[w][0]; v1 += S.wpart[w][1]; v2 += S.wpart[w][2];
                w0 += S.wpart[w][3]; w1 += S.wpart[w][4]; w2 += S.wpart[w][5];
                tr += S.wpart[w][6];
            }
            const float inv = 1.f/255.f;
            v0 *= inv; v1 *= inv; v2 *= inv;
            w0 *= inv; w1 *= inv; w2 *= inv;
            // v_x = vx0 + cross(w, vx0)   (linearity of the Levi-Civita term)
            float fx = v0 + (w1*v2 - w2*v1);
            float fy = v1 + (w2*v0 - w0*v2);
            float fz = v2 + (w0*v1 - w1*v0);
            g_vxf[bi*3+0] = fx; g_vxf[bi*3+1] = fy; g_vxf[bi*3+2] = fz;
            atomicAdd(&g_sumv[b*3+0], fx);
            atomicAdd(&g_sumv[b*3+1], fy);
            atomicAdd(&g_sumv[b*3+2], fz);
            atomicAdd(&g_trace[b], tr);
        }
    }
}

__global__ void k_final(float* __restrict__ out) {
    int b = blockIdx.x;
    int i = threadIdx.x;
    float m0 = g_sumv[b*3+0] * (1.f/NPT);
    float m1 = g_sumv[b*3+1] * (1.f/NPT);
    float m2 = g_sumv[b*3+2] * (1.f/NPT);
    out[b*STRIDE_B + i*3+0] = g_vxf[(b*NPT+i)*3+0] - m0;
    out[b*STRIDE_B + i*3+1] = g_vxf[(b*NPT+i)*3+1] - m1;
    out[b*STRIDE_B + i*3+2] = g_vxf[(b*NPT+i)*3+2] - m2;
    if (i == 0) out[BN*STRIDE_B + b] = g_trace[b] * (1.f/255.f);
}

extern "C" void kernel_launch(void* const* d_in, const int* in_sizes, int n_in,
                              void* d_out, int out_size) {
    (void)in_sizes; (void)n_in; (void)out_size;
    const float* state = (const float*)d_in[1];
    const float* mus   = (const float*)d_in[2];
    const float* gamma = (const float*)d_in[3];
    const float* s1W1  = (const float*)d_in[4];
    const float* s1b1  = (const float*)d_in[5];
    const float* s1W2  = (const float*)d_in[6];
    const float* s1b2  = (const float*)d_in[7];
    const float* s2W1  = (const float*)d_in[8];
    const float* s2b1  = (const float*)d_in[9];
    const float* s2W2  = (const float*)d_in[10];
    const float* s2b2  = (const float*)d_in[11];
    const float* fW1   = (const float*)d_in[12];
    const float* fb1   = (const float*)d_in[13];
    const float* fW2   = (const float*)d_in[14];
    const float* fb2   = (const float*)d_in[15];
    float* out = (float*)d_out;

    const size_t smem = sizeof(SmemLayout);
    cudaFuncSetAttribute(k_main, cudaFuncAttributeMaxDynamicSharedMemorySize, (int)smem);

    k_init<<<1, 64>>>();
    k_main<<<152, 256, smem>>>(state, mus, gamma,
                               s1W1, s1b1, s1W2, s1b2,
                               s2W1, s2b1, s2W2, s2b2,
                               fW1, fb1, fW2, fb2, out);
    k_final<<<BN, NPT>>>(out);
}

// round 3
// speedup vs baseline: 1.1528x; 1.1528x over previous
#include <cuda_runtime.h>

typedef unsigned long long ull;

#define BN 8
#define NPT 256
#define FF 32
#define NRBF_ 50
#define HH 128
#define NM1 255
#define NCOL 512
#define EPSV 1e-6f
#define STRIDE_B (NPT*3 + NPT*FF)   /* 8960 */
#define NCTA 152

__device__ float g_vxf[BN*NPT*3];
__device__ float g_tr[BN*NPT];
__device__ int   g_done = 0;

struct SmemLayout {
    float  Wc[NRBF_*NCOL];   // [k][512]: s1W1 | s2W1 | fW1 | mu*s1W1  (102400 B)
    float2 A2[NRBF_*64];     // rbf broadcast-packed [k][pair]          (25600 B)
    float  Wsum[3][FF*HH];   // feats->hidden summed weights            (49152 B)
    float  fW2s[HH*FF];      // second layer of f-net                   (16384 B)
    float  bsum[3][HH];
    float  fb2s[FF];
    float  xs[NPT*3];
    float  ms[NRBF_ + 2];
    float  pd[64];
    float  pr[64*3];
    float  feats_s[FF];
    float  smax[FF];
    float  cvec[3][HH];
    float  accst[8][HH];
    float  wpart[8][8];
    float  fin[BN*4];
    float  lastflag;
};

__device__ __forceinline__ float2 unpack2(ull v) {
    float2 r; asm("mov.b64 {%0, %1}, %2;" : "=f"(r.x), "=f"(r.y) : "l"(v)); return r;
}
__device__ __forceinline__ void ffma2(ull &d, ull a, ull b) {
    asm("fma.rn.f32x2 %0, %1, %2, %3;" : "=l"(d) : "l"(a), "l"(b), "l"(d));
}

__global__ __launch_bounds__(256, 1) void k_main(
    const float* __restrict__ state,
    const float* __restrict__ mus,
    const float* __restrict__ gammap,
    const float* __restrict__ s1W1, const float* __restrict__ s1b1,
    const float* __restrict__ s1W2, const float* __restrict__ s1b2,
    const float* __restrict__ s2W1, const float* __restrict__ s2b1,
    const float* __restrict__ s2W2, const float* __restrict__ s2b2,
    const float* __restrict__ fW1,  const float* __restrict__ fb1,
    const float* __restrict__ fW2,  const float* __restrict__ fb2,
    float* __restrict__ out)
{
    extern __shared__ char smraw[];
    SmemLayout& S = *reinterpret_cast<SmemLayout*>(smraw);
    const int tid = threadIdx.x;
    const int tx  = tid & 31;
    const int ty  = tid >> 5;
    const float gamma = gammap[0];
    const float n2g   = -2.0f * gamma;
    const float b2s1  = s1b2[0];
    const float b2s2  = s2b2[0];

    // ---- One-time per-CTA weight staging ----
    for (int e = tid; e < NRBF_*HH; e += 256) {
        int k = e >> 7, h = e & 127;
        float w1 = s1W1[e];
        S.Wc[k*NCOL + h]       = w1;
        S.Wc[k*NCOL + 128 + h] = s2W1[e];
        S.Wc[k*NCOL + 256 + h] = fW1[e];
        S.Wc[k*NCOL + 384 + h] = mus[k] * w1;
    }
    for (int e = tid; e < FF*HH; e += 256) {
        S.Wsum[0][e] = s1W1[NRBF_*HH + e] + s1W1[(NRBF_+FF)*HH + e];
        S.Wsum[1][e] = s2W1[NRBF_*HH + e] + s2W1[(NRBF_+FF)*HH + e];
        S.Wsum[2][e] = fW1[NRBF_*HH + e];
    }
    for (int e = tid; e < HH*FF; e += 256) S.fW2s[e] = fW2[e];
    if (tid < HH) {
        S.bsum[0][tid] = s1b1[tid];
        S.bsum[1][tid] = s2b1[tid];
        S.bsum[2][tid] = fb1[tid];
    }
    if (tid < FF)    S.fb2s[tid] = fb2[tid];
    if (tid < NRBF_) S.ms[tid]   = mus[tid];

    float w2s1v[4], w2s2v[4];
    #pragma unroll
    for (int q = 0; q < 4; q++) {
        w2s1v[q] = s1W2[tx*4 + q];
        w2s2v[q] = s2W2[tx*4 + q];
    }

    for (int bi = blockIdx.x; bi < BN*NPT; bi += gridDim.x) {
        const int b = bi >> 8;
        const int i = bi & 255;
        const float* st = state + b*STRIDE_B;
        __syncthreads();   // also covers weight staging on first iter
        for (int e = tid; e < NPT*3; e += 256) S.xs[e] = st[e];
        if (tid < FF) S.feats_s[tid] = st[NPT*3 + i*FF + tid];
        __syncthreads();

        if (ty == 0) {  // softmax(feats_i) over F=32 by warp 0
            float v = S.feats_s[tx];
            float m = v;
            #pragma unroll
            for (int o = 16; o; o >>= 1) m = fmaxf(m, __shfl_xor_sync(0xffffffffu, m, o));
            float e = __expf(v - m);
            float s = e;
            #pragma unroll
            for (int o = 16; o; o >>= 1) s += __shfl_xor_sync(0xffffffffu, s, o);
            S.smax[tx] = e / s;
        }
        __syncthreads();

        // Per-(b,i) constant part of hidden pre-activations, computed once
        // cooperatively (3 nets x 128 h over 256 threads, all from SMEM)
        for (int idx = tid; idx < 3*HH; idx += 256) {
            int net = idx >> 7, h = idx & 127;
            const float* wv = (net < 2) ? S.feats_s : S.smax;
            const float* Wn = S.Wsum[net];
            float c = S.bsum[net][h];
            #pragma unroll
            for (int f = 0; f < FF; f++) c += wv[f] * Wn[f*HH + h];
            S.cvec[net][h] = c;
        }
        __syncthreads();

        float c1[4], c2[4], cf[4];
        #pragma unroll
        for (int q = 0; q < 4; q++) {
            c1[q] = S.cvec[0][tx*4 + q];
            c2[q] = S.cvec[1][tx*4 + q];
            cf[q] = S.cvec[2][tx*4 + q];
        }
        const float xi0 = S.xs[i*3+0], xi1 = S.xs[i*3+1], xi2 = S.xs[i*3+2];

        float accf0=0.f, accf1=0.f, accf2=0.f, accf3=0.f;
        float vx0=0.f, vy0=0.f, vz0=0.f;
        float wxa=0.f, wya=0.f, wza=0.f;
        float trc=0.f;

        for (int tile = 0; tile < 4; tile++) {
            if (tid < 64) {
                int gp = tile*64 + tid;
                float r0 = 0.f, r1 = 0.f, r2 = 0.f;
                if (gp < NM1) {
                    int j = (gp < i) ? gp : gp + 1;
                    r0 = xi0 - S.xs[j*3+0];
                    r1 = xi1 - S.xs[j*3+1];
                    r2 = xi2 - S.xs[j*3+2];
                }
                S.pd[tid] = sqrtf(r0*r0 + r1*r1 + r2*r2 + EPSV);
                S.pr[tid*3+0] = r0; S.pr[tid*3+1] = r1; S.pr[tid*3+2] = r2;
            }
            __syncthreads();
            for (int e = tid; e < NRBF_*64; e += 256) {
                int k = e >> 6, p = e & 63;
                float t = S.pd[p] - S.ms[k];
                float v = __expf(-gamma * t * t);
                S.A2[e] = make_float2(v, v);
            }
            __syncthreads();

            // GEMM: [64 x 50] @ [50 x 512] with f32x2 packed FMA
            ull acc[4][8][2];
            #pragma unroll
            for (int j = 0; j < 4; j++)
                #pragma unroll
                for (int p = 0; p < 8; p++) { acc[j][p][0] = 0ull; acc[j][p][1] = 0ull; }

            const ull* Arow = reinterpret_cast<const ull*>(S.A2) + ty*8;
            const ull* Wu   = reinterpret_cast<const ull*>(S.Wc) + tx*2;
            #pragma unroll 5
            for (int k = 0; k < NRBF_; k++) {
                ull av[8];
                #pragma unroll
                for (int p = 0; p < 8; p++) av[p] = Arow[k*64 + p];
                #pragma unroll
                for (int j = 0; j < 4; j++) {
                    ulonglong2 bv = *reinterpret_cast<const ulonglong2*>(Wu + k*256 + j*64);
                    #pragma unroll
                    for (int p = 0; p < 8; p++) {
                        ffma2(acc[j][p][0], bv.x, av[p]);
                        ffma2(acc[j][p][1], bv.y, av[p]);
                    }
                }
            }

            // Epilogue: silu / s1 / s2 / exact d-gradient, warp reductions
            #pragma unroll
            for (int p = 0; p < 8; p++) {
                int lp = ty*8 + p;
                int gp = tile*64 + lp;
                float d  = S.pd[lp];
                float r0 = S.pr[lp*3+0], r1 = S.pr[lp*3+1], r2 = S.pr[lp*3+2];
                float s1part = 0.f, s2part = 0.f, gpart = 0.f;
                float afq[4];
                #pragma unroll
                for (int half = 0; half < 2; half++) {
                    float2 v1 = unpack2(acc[0][p][half]);
                    float2 v2 = unpack2(acc[1][p][half]);
                    float2 vf = unpack2(acc[2][p][half]);
                    float2 vp = unpack2(acc[3][p][half]);
                    #pragma unroll
                    for (int sub = 0; sub < 2; sub++) {
                        int q = half*2 + sub;
                        float phi1 = sub ? v1.y : v1.x;
                        float phi2 = sub ? v2.y : v2.x;
                        float phif = sub ? vf.y : vf.x;
                        float psi  = sub ? vp.y : vp.x;
                        float pre1 = phi1 + c1[q];
                        float sig1 = __fdividef(1.f, 1.f + __expf(-pre1));
                        s1part += pre1 * sig1 * w2s1v[q];
                        float dsil = sig1 * (1.f + pre1 * (1.f - sig1));
                        float tq = n2g * (d * phi1 - psi);
                        gpart += w2s1v[q] * dsil * tq;
                        float pre2 = phi2 + c2[q];
                        float sig2 = __fdividef(1.f, 1.f + __expf(-pre2));
                        s2part += pre2 * sig2 * w2s2v[q];
                        float pref = phif + cf[q];
                        float sigf = __fdividef(1.f, 1.f + __expf(-pref));
                        afq[q] = pref * sigf;
                    }
                }
                #pragma unroll
                for (int o = 16; o; o >>= 1) {
                    s1part += __shfl_xor_sync(0xffffffffu, s1part, o);
                    s2part += __shfl_xor_sync(0xffffffffu, s2part, o);
                    gpart  += __shfl_xor_sync(0xffffffffu, gpart,  o);
                }
                if (gp < NM1) {
                    float s1 = s1part + b2s1;
                    float s2 = s2part + b2s2;
                    float r2d = __fdividef(d*d - EPSV, d);   // |r|^2 / d
                    vx0 += r0*s1; vy0 += r1*s1; vz0 += r2*s1;
                    wxa += r0*s2; wya += r1*s2; wza += r2*s2;
                    trc += r2d * gpart + 3.f * s1;
                    accf0 += afq[0]; accf1 += afq[1]; accf2 += afq[2]; accf3 += afq[3];
                }
            }
            __syncthreads();
        } // tiles

        // Combine per-warp partials
        S.accst[ty][tx*4+0] = accf0;
        S.accst[ty][tx*4+1] = accf1;
        S.accst[ty][tx*4+2] = accf2;
        S.accst[ty][tx*4+3] = accf3;
        if (tx == 0) {
            S.wpart[ty][0] = vx0; S.wpart[ty][1] = vy0; S.wpart[ty][2] = vz0;
            S.wpart[ty][3] = wxa; S.wpart[ty][4] = wya; S.wpart[ty][5] = wza;
            S.wpart[ty][6] = trc;
        }
        __syncthreads();
        if (tid < HH) {
            float t = 0.f;
            #pragma unroll
            for (int w = 0; w < 8; w++) t += S.accst[w][tid];
            S.accst[0][tid] = t;
        }
        __syncthreads();
        if (tid < FF) {
            float s = 0.f;
            for (int h = 0; h < HH; h++) s += S.accst[0][h] * S.fW2s[h*FF + tid];
            out[b*STRIDE_B + NPT*3 + i*FF + tid] = S.fb2s[tid] + s * (1.f/255.f);
        }
        if (tid == 0) {
            float v0=0,v1=0,v2=0,w0=0,w1=0,w2=0,tr=0;
            #pragma unroll
            for (int w = 0; w < 8; w++) {
                v0 += S.wpart[w][0]; v1 += S.wpart[w][1]; v2 += S.wpart[w][2];
                w0 += S.wpart[w][3]; w1 += S.wpart[w][4]; w2 += S.wpart[w][5];
                tr += S.wpart[w][6];
            }
            const float inv = 1.f/255.f;
            v0 *= inv; v1 *= inv; v2 *= inv;
            w0 *= inv; w1 *= inv; w2 *= inv;
            // v_x = vx0 + cross(w, vx0)   (linearity of the Levi-Civita term)
            float fx = v0 + (w1*v2 - w2*v1);
            float fy = v1 + (w2*v0 - w0*v2);
            float fz = v2 + (w0*v1 - w1*v0);
            g_vxf[bi*3+0] = fx; g_vxf[bi*3+1] = fy; g_vxf[bi*3+2] = fz;
            g_tr[bi] = tr * inv;
        }
    }

    // ---- Last-block finalization: mean removal + trace ----
    __syncthreads();
    if (tid == 0) {
        __threadfence();
        int v = atomicAdd(&g_done, 1);
        S.lastflag = (v == (int)gridDim.x - 1) ? 1.f : 0.f;
    }
    __syncthreads();
    if (S.lastflag != 0.f) {
        __threadfence();
        // warp ty sums batch b = ty
        float s0 = 0.f, s1 = 0.f, s2 = 0.f, st = 0.f;
        for (int ii = tx; ii < NPT; ii += 32) {
            int e = ty*NPT + ii;
            s0 += g_vxf[e*3+0]; s1 += g_vxf[e*3+1]; s2 += g_vxf[e*3+2];
            st += g_tr[e];
        }
        #pragma unroll
        for (int o = 16; o; o >>= 1) {
            s0 += __shfl_xor_sync(0xffffffffu, s0, o);
            s1 += __shfl_xor_sync(0xffffffffu, s1, o);
            s2 += __shfl_xor_sync(0xffffffffu, s2, o);
            st += __shfl_xor_sync(0xffffffffu, st, o);
        }
        if (tx == 0) {
            S.fin[ty*4+0] = s0 * (1.f/NPT);
            S.fin[ty*4+1] = s1 * (1.f/NPT);
            S.fin[ty*4+2] = s2 * (1.f/NPT);
            S.fin[ty*4+3] = st;
        }
        __syncthreads();
        for (int e = tid; e < BN*NPT; e += 256) {
            int bb = e >> 8, ii = e & 255;
            float m0 = S.fin[bb*4+0], m1 = S.fin[bb*4+1], m2 = S.fin[bb*4+2];
            out[bb*STRIDE_B + ii*3+0] = g_vxf[e*3+0] - m0;
            out[bb*STRIDE_B + ii*3+1] = g_vxf[e*3+1] - m1;
            out[bb*STRIDE_B + ii*3+2] = g_vxf[e*3+2] - m2;
        }
        if (tid < BN) out[BN*STRIDE_B + tid] = S.fin[tid*4+3];
        if (tid == 0) g_done = 0;   // self-reset for next launch
    }
}

extern "C" void kernel_launch(void* const* d_in, const int* in_sizes, int n_in,
                              void* d_out, int out_size) {
    (void)in_sizes; (void)n_in; (void)out_size;
    const float* state = (const float*)d_in[1];
    const float* mus   = (const float*)d_in[2];
    const float* gamma = (const float*)d_in[3];
    const float* s1W1  = (const float*)d_in[4];
    const float* s1b1  = (const float*)d_in[5];
    const float* s1W2  = (const float*)d_in[6];
    const float* s1b2  = (const float*)d_in[7];
    const float* s2W1  = (const float*)d_in[8];
    const float* s2b1  = (const float*)d_in[9];
    const float* s2W2  = (const float*)d_in[10];
    const float* s2b2  = (const float*)d_in[11];
    const float* fW1   = (const float*)d_in[12];
    const float* fb1   = (const float*)d_in[13];
    const float* fW2   = (const float*)d_in[14];
    const float* fb2   = (const float*)d_in[15];
    float* out = (float*)d_out;

    const size_t smem = sizeof(SmemLayout);
    cudaFuncSetAttribute(k_main, cudaFuncAttributeMaxDynamicSharedMemorySize, (int)smem);

    k_main<<<NCTA, 256, smem>>>(state, mus, gamma,
                                s1W1, s1b1, s1W2, s1b2,
                                s2W1, s2b1, s2W2, s2b2,
                                fW1, fb1, fW2, fb2, out);
}